// round 7
// baseline (speedup 1.0000x reference)
#include <cuda_runtime.h>
#include <cuda_bf16.h>
#include <math.h>
#include <stdint.h>

#define NROWS 8192
#define DDIM  64
#define KSIZE 128.0
#define SIGMA 3.0
#define EPSV  1e-5

// ---------------------------------------------------------------------------
// Device-global scratch (no allocation allowed in kernel_launch)
// ---------------------------------------------------------------------------
__device__ double g_sums[6];
__device__ float  g_rl[3 * NROWS];                              // -|x|^2/(128 ln2)
__device__ __align__(16) __nv_bfloat16 g_bf[3 * NROWS * DDIM];  // bf16 copies

// ---------------------------------------------------------------------------
static __device__ __forceinline__ uint32_t smem_u32(const void* p) {
    uint32_t a;
    asm("{ .reg .u64 t; cvta.to.shared.u64 t, %1; cvt.u32.u64 %0, t; }"
        : "=r"(a) : "l"(p));
    return a;
}
static __device__ __forceinline__ float ex2f(float x) {
    float r; asm("ex2.approx.ftz.f32 %0, %1;" : "=f"(r) : "f"(x)); return r;
}
// Pack two f32 -> f16x2, one MUFU ex2 for both, unpack to f32.
static __device__ __forceinline__ void ex2_pair(float t0, float t1,
                                                float& e0, float& e1) {
    uint32_t h, e;
    asm("cvt.rn.f16x2.f32 %0, %1, %2;" : "=r"(h) : "f"(t1), "f"(t0));
    asm("ex2.approx.f16x2 %0, %1;" : "=r"(e) : "r"(h));
    asm("{ .reg .f16 l, u; mov.b32 {l, u}, %2;\n\t"
        "cvt.f32.f16 %0, l; cvt.f32.f16 %1, u; }"
        : "=f"(e0), "=f"(e1) : "r"(e));
}
static __device__ __forceinline__ void ldsm_x4(uint32_t* r, uint32_t addr) {
    asm volatile("ldmatrix.sync.aligned.m8n8.x4.shared.b16 {%0,%1,%2,%3}, [%4];"
                 : "=r"(r[0]), "=r"(r[1]), "=r"(r[2]), "=r"(r[3]) : "r"(addr));
}
static __device__ __forceinline__ void mma16816(float* d, const uint32_t* a,
                                                uint32_t b0, uint32_t b1) {
    asm volatile(
        "mma.sync.aligned.m16n8k16.row.col.f32.bf16.bf16.f32 "
        "{%0,%1,%2,%3}, {%4,%5,%6,%7}, {%8,%9}, {%0,%1,%2,%3};"
        : "+f"(d[0]), "+f"(d[1]), "+f"(d[2]), "+f"(d[3])
        : "r"(a[0]), "r"(a[1]), "r"(a[2]), "r"(a[3]), "r"(b0), "r"(b1));
}
static __device__ __forceinline__ void cp16(uint32_t dst, const void* src) {
    asm volatile("cp.async.cg.shared.global [%0], [%1], 16;" :: "r"(dst), "l"(src));
}
#define CP_COMMIT() asm volatile("cp.async.commit_group;" ::: "memory")
#define CP_WAIT(n)  asm volatile("cp.async.wait_group %0;" :: "n"(n) : "memory")

// ---------------------------------------------------------------------------
// Fused prep: bf16 convert + row norms (+ zero the 6 accumulators).
// ---------------------------------------------------------------------------
__global__ void fused_prep(const float* __restrict__ m0,
                           const float* __restrict__ m1,
                           const float* __restrict__ m2) {
    const int tid = threadIdx.x;
    if (blockIdx.x == 0 && tid < 6) g_sums[tid] = 0.0;

    const int gw   = blockIdx.x * 8 + (tid >> 5);   // global warp = row id
    const int lane = tid & 31;
    if (gw >= 3 * NROWS) return;
    const int mod = gw / NROWS;
    const int row = gw - mod * NROWS;
    const float* src = (mod == 0) ? m0 : (mod == 1) ? m1 : m2;

    float2 v = ((const float2*)(src + (size_t)row * DDIM))[lane];
    __nv_bfloat162* dst = (__nv_bfloat162*)(g_bf + (size_t)gw * DDIM);
    dst[lane] = __float22bfloat162_rn(v);

    float s = v.x * v.x + v.y * v.y;
    #pragma unroll
    for (int off = 16; off > 0; off >>= 1)
        s += __shfl_down_sync(0xffffffffu, s, off);
    if (lane == 0) g_rl[gw] = s * (float)(-1.0 / (128.0 * M_LN2));
}

// ---------------------------------------------------------------------------
// One 64x32 warp tile vs K=64: A (64 rows) in shared smem, B (32 rows) in the
// warp's private smem slice. Epilogue uses paired f16x2 ex2 (half the MUFU).
// ---------------------------------------------------------------------------
static __device__ __forceinline__ float tile_compute(
    uint32_t baseA, uint32_t baseB, const float* ra,
    const float* __restrict__ rlB, float lw, int lane)
{
    const int tig  = lane & 3;
    const int a_r  = lane & 15;
    const int a_kh = lane >> 4;
    const int b_r  = (lane & 7) + ((lane & 16) >> 1);
    const int b_kh = (lane >> 3) & 1;

    float d[4][4][4];
    #pragma unroll
    for (int mf = 0; mf < 4; mf++)
        #pragma unroll
        for (int nf = 0; nf < 4; nf++)
            #pragma unroll
            for (int q = 0; q < 4; q++) d[mf][nf][q] = 0.0f;

    #pragma unroll
    for (int ks = 0; ks < 4; ks++) {
        uint32_t a[4][4];
        #pragma unroll
        for (int mf = 0; mf < 4; mf++) {
            int row = mf * 16 + a_r;
            int kc = ks * 2 + a_kh;
            ldsm_x4(a[mf], baseA + row * 128 + ((kc ^ (row & 7)) << 4));
        }
        uint32_t b[2][4];
        #pragma unroll
        for (int bf = 0; bf < 2; bf++) {
            int row = bf * 16 + b_r;
            int kc = ks * 2 + b_kh;
            ldsm_x4(b[bf], baseB + row * 128 + ((kc ^ (row & 7)) << 4));
        }
        #pragma unroll
        for (int mf = 0; mf < 4; mf++)
            #pragma unroll
            for (int nf = 0; nf < 4; nf++)
                mma16816(d[mf][nf], a[mf],
                         b[nf >> 1][(nf & 1) * 2], b[nf >> 1][(nf & 1) * 2 + 1]);
    }

    const float C2 = (float)(1.0 / (64.0 * M_LN2));
    float pb[4][2];
    #pragma unroll
    for (int nf = 0; nf < 4; nf++) {
        pb[nf][0] = ex2f(rlB[nf * 8 + tig * 2] + lw);
        pb[nf][1] = ex2f(rlB[nf * 8 + tig * 2 + 1] + lw);
    }

    float s0 = 0.0f, s1 = 0.0f, s2 = 0.0f, s3 = 0.0f;
    #pragma unroll
    for (int mf = 0; mf < 4; mf++)
        #pragma unroll
        for (int nf = 0; nf < 4; nf++) {
            float t0 = fmaf(d[mf][nf][0], C2, ra[2 * mf]);
            float t1 = fmaf(d[mf][nf][1], C2, ra[2 * mf]);
            float t2 = fmaf(d[mf][nf][2], C2, ra[2 * mf + 1]);
            float t3 = fmaf(d[mf][nf][3], C2, ra[2 * mf + 1]);
            float e0, e1, e2, e3;
            ex2_pair(t0, t1, e0, e1);
            ex2_pair(t2, t3, e2, e3);
            s0 = fmaf(e0, pb[nf][0], s0);
            s1 = fmaf(e1, pb[nf][1], s1);
            s2 = fmaf(e2, pb[nf][0], s2);
            s3 = fmaf(e3, pb[nf][1], s3);
        }
    return (s0 + s1) + (s2 + s3);
}

// ---------------------------------------------------------------------------
// Main Gram kernel: per-warp independent pipelines, no block sync in mainloop.
// grid = (16, 128, 6): bjs (16 x 32-col slices = 512 cols), bi (64 rows), pair.
// CTA = 4 warps; A (64 rows, 8 KB) shared, loaded once. Each warp owns 4
// consecutive 32-col B slices, double-buffered in private smem via its own
// cp.async groups. Symmetric pairs at 32-col granularity: j < 2bi skip,
// j in {2bi, 2bi+1} weight 1, j > 2bi+1 weight 2 (folded as +1 in exponent).
// ---------------------------------------------------------------------------
__global__ __launch_bounds__(128, 4) void gram_mma() {
    const int pz = blockIdx.z;
    const int pa_[6] = {0, 1, 2, 0, 0, 1};
    const int pb_[6] = {0, 1, 2, 1, 2, 2};
    const int ia = pa_[pz], ib = pb_[pz];
    const int bi = blockIdx.y, bjs = blockIdx.x;
    const bool sym = (pz < 3);
    if (sym && bjs * 16 + 15 < 2 * bi) return;       // whole CTA below diagonal

    __shared__ __align__(128) uint4 smA[512];        // 64 rows x 8 chunks, 8 KB
    __shared__ __align__(128) uint4 smB[4][2][256];  // per-warp double buffer

    const int tid = threadIdx.x;
    const int wid = tid >> 5, lane = tid & 31;
    const int j0 = bjs * 16 + wid * 4;               // this warp's first slice

    const uint4* Ag = (const uint4*)(g_bf + (size_t)ia * NROWS * DDIM) + (size_t)bi * 512;
    const uint4* Bbase = (const uint4*)(g_bf + (size_t)ib * NROWS * DDIM);

    const uint32_t baseA = smem_u32(smA);
    const uint32_t baseB[2] = { smem_u32(smB[wid][0]), smem_u32(smB[wid][1]) };

    // --- Prologue ---------------------------------------------------------
    #pragma unroll
    for (int q = 0; q < 4; q++) {
        int c = tid + 128 * q;
        int row = c >> 3, kc = c & 7;
        cp16(baseA + (uint32_t)(row * 8 + (kc ^ (row & 7))) * 16u, Ag + c);
    }
    #pragma unroll
    for (int t0 = 0; t0 < 2; t0++) {
        int j = j0 + t0;
        if (!(sym && j < 2 * bi)) {
            #pragma unroll
            for (int q = 0; q < 8; q++) {
                int c = lane + 32 * q;
                int row = c >> 3, kc = c & 7;
                cp16(baseB[t0] + (uint32_t)(row * 8 + (kc ^ (row & 7))) * 16u,
                     Bbase + (size_t)j * 256 + c);
            }
        }
        CP_COMMIT();
    }

    // Per-thread A-row exponent terms
    const int g = lane >> 2;
    const float* rlA = g_rl + ia * NROWS + bi * 64;
    float ra[8];
    #pragma unroll
    for (int mf = 0; mf < 4; mf++) {
        ra[2 * mf]     = rlA[mf * 16 + g];
        ra[2 * mf + 1] = rlA[mf * 16 + g + 8];
    }

    float s = 0.0f;

    // --- Mainloop: warp-private, no block sync ----------------------------
    #pragma unroll
    for (int t = 0; t < 4; t++) {
        const int j = j0 + t;
        CP_WAIT(1);                     // group t complete (t+1 may be pending)
        if (t == 0) __syncthreads();    // A visible CTA-wide (once)
        else        __syncwarp();
        if (!(sym && j < 2 * bi)) {
            const float lw = (sym && j > 2 * bi + 1) ? 1.0f : 0.0f;
            s += tile_compute(baseA, baseB[t & 1], ra,
                              g_rl + ib * NROWS + j * 32, lw, lane);
        }
        if (t < 2) {                    // prefetch slice t+2 into buf[t&1]
            int jn = j0 + t + 2;
            if (!(sym && jn < 2 * bi)) {
                #pragma unroll
                for (int q = 0; q < 8; q++) {
                    int c = lane + 32 * q;
                    int row = c >> 3, kc = c & 7;
                    cp16(baseB[t & 1] + (uint32_t)(row * 8 + (kc ^ (row & 7))) * 16u,
                         Bbase + (size_t)jn * 256 + c);
                }
            }
        }
        CP_COMMIT();                    // uniform group count (may be empty)
    }

    // Warp reduce -> one double atomic per warp
    #pragma unroll
    for (int off = 16; off > 0; off >>= 1)
        s += __shfl_down_sync(0xffffffffu, s, off);
    if (lane == 0)
        atomicAdd(&g_sums[pz], (double)s);
}

// ---------------------------------------------------------------------------
// Epilogue: 3 log-ratio terms in double
// ---------------------------------------------------------------------------
__global__ void finish_kernel(float* __restrict__ out) {
    const double norm = sqrt(2.0 * M_PI * KSIZE);
    const double inv  = 1.0 / ((double)NROWS * (double)NROWS * norm);
    double m[6];
    #pragma unroll
    for (int q = 0; q < 6; q++) m[q] = g_sums[q] * inv;
    double loss = 0.0;
    loss += log(SIGMA * sqrt(m[0] * m[1] + EPSV) / (m[3] + EPSV));
    loss += log(SIGMA * sqrt(m[0] * m[2] + EPSV) / (m[4] + EPSV));
    loss += log(SIGMA * sqrt(m[1] * m[2] + EPSV) / (m[5] + EPSV));
    out[0] = (float)loss;
}

// ---------------------------------------------------------------------------
extern "C" void kernel_launch(void* const* d_in, const int* in_sizes, int n_in,
                              void* d_out, int out_size) {
    const float* m0 = (const float*)d_in[0];
    const float* m1 = (const float*)d_in[1];
    const float* m2 = (const float*)d_in[2];
    float* out = (float*)d_out;

    fused_prep<<<(3 * NROWS) / 8, 256>>>(m0, m1, m2);
    gram_mma<<<dim3(16, 128, 6), 128>>>();
    finish_kernel<<<1, 1>>>(out);
}

// round 8
// speedup vs baseline: 1.0647x; 1.0647x over previous
#include <cuda_runtime.h>
#include <cuda_bf16.h>
#include <math.h>
#include <stdint.h>

#define NROWS 8192
#define DDIM  64
#define KSIZE 128.0
#define SIGMA 3.0
#define EPSV  1e-5

// ---------------------------------------------------------------------------
// Device-global scratch (no allocation allowed in kernel_launch)
// ---------------------------------------------------------------------------
__device__ double g_sums[6];
__device__ float  g_rl[3 * NROWS];                              // -|x|^2/(128 ln2)
__device__ __align__(16) __nv_bfloat16 g_bf[3 * NROWS * DDIM];  // bf16 copies

// ---------------------------------------------------------------------------
static __device__ __forceinline__ uint32_t smem_u32(const void* p) {
    uint32_t a;
    asm("{ .reg .u64 t; cvta.to.shared.u64 t, %1; cvt.u32.u64 %0, t; }"
        : "=r"(a) : "l"(p));
    return a;
}
static __device__ __forceinline__ uint32_t pack_h2(float lo, float hi) {
    uint32_t r; asm("cvt.rn.f16x2.f32 %0, %1, %2;" : "=r"(r) : "f"(hi), "f"(lo));
    return r;
}
static __device__ __forceinline__ uint32_t ex2_h2(uint32_t x) {
    uint32_t r; asm("ex2.approx.f16x2 %0, %1;" : "=r"(r) : "r"(x));
    return r;
}
static __device__ __forceinline__ uint32_t hfma2(uint32_t a, uint32_t b, uint32_t c) {
    uint32_t r; asm("fma.rn.f16x2 %0, %1, %2, %3;" : "=r"(r) : "r"(a), "r"(b), "r"(c));
    return r;
}
static __device__ __forceinline__ float unpack_sum_h2(uint32_t p) {
    float lo, hi;
    asm("{ .reg .f16 l, u; mov.b32 {l, u}, %2;\n\t"
        "cvt.f32.f16 %0, l; cvt.f32.f16 %1, u; }"
        : "=f"(lo), "=f"(hi) : "r"(p));
    return lo + hi;
}
static __device__ __forceinline__ void ldsm_x4(uint32_t* r, uint32_t addr) {
    asm volatile("ldmatrix.sync.aligned.m8n8.x4.shared.b16 {%0,%1,%2,%3}, [%4];"
                 : "=r"(r[0]), "=r"(r[1]), "=r"(r[2]), "=r"(r[3]) : "r"(addr));
}
static __device__ __forceinline__ void mma16816(float* d, const uint32_t* a,
                                                uint32_t b0, uint32_t b1) {
    asm volatile(
        "mma.sync.aligned.m16n8k16.row.col.f32.bf16.bf16.f32 "
        "{%0,%1,%2,%3}, {%4,%5,%6,%7}, {%8,%9}, {%0,%1,%2,%3};"
        : "+f"(d[0]), "+f"(d[1]), "+f"(d[2]), "+f"(d[3])
        : "r"(a[0]), "r"(a[1]), "r"(a[2]), "r"(a[3]), "r"(b0), "r"(b1));
}
static __device__ __forceinline__ void cp16(uint32_t dst, const void* src) {
    asm volatile("cp.async.cg.shared.global [%0], [%1], 16;" :: "r"(dst), "l"(src));
}
#define CP_COMMIT() asm volatile("cp.async.commit_group;" ::: "memory")
#define CP_WAIT(n)  asm volatile("cp.async.wait_group %0;" :: "n"(n) : "memory")

// ---------------------------------------------------------------------------
// Fused prep: bf16 convert + row norms (+ zero the 6 accumulators).
// ---------------------------------------------------------------------------
__global__ void fused_prep(const float* __restrict__ m0,
                           const float* __restrict__ m1,
                           const float* __restrict__ m2) {
    const int tid = threadIdx.x;
    if (blockIdx.x == 0 && tid < 6) g_sums[tid] = 0.0;

    const int gw   = blockIdx.x * 8 + (tid >> 5);   // global warp = row id
    const int lane = tid & 31;
    if (gw >= 3 * NROWS) return;
    const int mod = gw / NROWS;
    const int row = gw - mod * NROWS;
    const float* src = (mod == 0) ? m0 : (mod == 1) ? m1 : m2;

    float2 v = ((const float2*)(src + (size_t)row * DDIM))[lane];
    __nv_bfloat162* dst = (__nv_bfloat162*)(g_bf + (size_t)gw * DDIM);
    dst[lane] = __float22bfloat162_rn(v);

    float s = v.x * v.x + v.y * v.y;
    #pragma unroll
    for (int off = 16; off > 0; off >>= 1)
        s += __shfl_down_sync(0xffffffffu, s, off);
    if (lane == 0) g_rl[gw] = s * (float)(-1.0 / (128.0 * M_LN2));
}

// ---------------------------------------------------------------------------
// One 64x32 warp tile vs K=64. Epilogue fully in f16x2:
//   pack(d0,d1) -> hfma2(t = d*C2 + ra) -> ex2.f16x2 -> hfma2(acc += e * pb)
// 4 ops per 2 elements; unpack only at tile end.
// ---------------------------------------------------------------------------
static __device__ __forceinline__ float tile_compute(
    uint32_t baseA, uint32_t baseB, const uint32_t* rah,
    const float* __restrict__ rlB, float lw, int lane)
{
    const int tig  = lane & 3;
    const int a_r  = lane & 15;
    const int a_kh = lane >> 4;
    const int b_r  = (lane & 7) + ((lane & 16) >> 1);
    const int b_kh = (lane >> 3) & 1;

    float d[4][4][4];
    #pragma unroll
    for (int mf = 0; mf < 4; mf++)
        #pragma unroll
        for (int nf = 0; nf < 4; nf++)
            #pragma unroll
            for (int q = 0; q < 4; q++) d[mf][nf][q] = 0.0f;

    #pragma unroll
    for (int ks = 0; ks < 4; ks++) {
        uint32_t a[4][4];
        #pragma unroll
        for (int mf = 0; mf < 4; mf++) {
            int row = mf * 16 + a_r;
            int kc = ks * 2 + a_kh;
            ldsm_x4(a[mf], baseA + row * 128 + ((kc ^ (row & 7)) << 4));
        }
        uint32_t b[2][4];
        #pragma unroll
        for (int bf = 0; bf < 2; bf++) {
            int row = bf * 16 + b_r;
            int kc = ks * 2 + b_kh;
            ldsm_x4(b[bf], baseB + row * 128 + ((kc ^ (row & 7)) << 4));
        }
        #pragma unroll
        for (int mf = 0; mf < 4; mf++)
            #pragma unroll
            for (int nf = 0; nf < 4; nf++)
                mma16816(d[mf][nf], a[mf],
                         b[nf >> 1][(nf & 1) * 2], b[nf >> 1][(nf & 1) * 2 + 1]);
    }

    // Per-column factor pb = 2^(rb + lw), packed f16x2 per nf.
    const float C2 = (float)(1.0 / (64.0 * M_LN2));
    const uint32_t C2h = pack_h2(C2, C2);
    uint32_t pbh[4];
    #pragma unroll
    for (int nf = 0; nf < 4; nf++)
        pbh[nf] = ex2_h2(pack_h2(rlB[nf * 8 + tig * 2] + lw,
                                 rlB[nf * 8 + tig * 2 + 1] + lw));

    uint32_t acc[4] = {0u, 0u, 0u, 0u};     // 4 independent f16x2 accumulators
    #pragma unroll
    for (int mf = 0; mf < 4; mf++)
        #pragma unroll
        for (int nf = 0; nf < 4; nf++) {
            uint32_t h01 = pack_h2(d[mf][nf][0], d[mf][nf][1]);
            uint32_t h23 = pack_h2(d[mf][nf][2], d[mf][nf][3]);
            uint32_t e01 = ex2_h2(hfma2(h01, C2h, rah[2 * mf]));
            uint32_t e23 = ex2_h2(hfma2(h23, C2h, rah[2 * mf + 1]));
            acc[(mf & 1) * 2]     = hfma2(e01, pbh[nf], acc[(mf & 1) * 2]);
            acc[(mf & 1) * 2 + 1] = hfma2(e23, pbh[nf], acc[(mf & 1) * 2 + 1]);
        }

    return (unpack_sum_h2(acc[0]) + unpack_sum_h2(acc[1])) +
           (unpack_sum_h2(acc[2]) + unpack_sum_h2(acc[3]));
}

// ---------------------------------------------------------------------------
// Main Gram kernel: per-warp independent pipelines (round-6 structure).
// grid = (16, 128, 6): bjs (16 x 32-col slices), bi (64 rows), pair.
// CTA = 4 warps; A (64 rows, 8 KB) shared; each warp owns 4 consecutive
// 32-col B slices, double-buffered in private smem via its own cp.async
// groups. Symmetric pairs at 32-col granularity: j < 2bi skip, j in
// {2bi, 2bi+1} weight 1, j > 2bi+1 weight 2 (folded as +1 in exponent).
// ---------------------------------------------------------------------------
__global__ __launch_bounds__(128, 4) void gram_mma() {
    const int pz = blockIdx.z;
    const int pa_[6] = {0, 1, 2, 0, 0, 1};
    const int pb_[6] = {0, 1, 2, 1, 2, 2};
    const int ia = pa_[pz], ib = pb_[pz];
    const int bi = blockIdx.y, bjs = blockIdx.x;
    const bool sym = (pz < 3);
    if (sym && bjs * 16 + 15 < 2 * bi) return;       // whole CTA below diagonal

    __shared__ __align__(128) uint4 smA[512];        // 64 rows x 8 chunks, 8 KB
    __shared__ __align__(128) uint4 smB[4][2][256];  // per-warp double buffer

    const int tid = threadIdx.x;
    const int wid = tid >> 5, lane = tid & 31;
    const int j0 = bjs * 16 + wid * 4;               // this warp's first slice

    const uint4* Ag = (const uint4*)(g_bf + (size_t)ia * NROWS * DDIM) + (size_t)bi * 512;
    const uint4* Bbase = (const uint4*)(g_bf + (size_t)ib * NROWS * DDIM);

    const uint32_t baseA = smem_u32(smA);
    const uint32_t baseB[2] = { smem_u32(smB[wid][0]), smem_u32(smB[wid][1]) };

    // --- Prologue ---------------------------------------------------------
    #pragma unroll
    for (int q = 0; q < 4; q++) {
        int c = tid + 128 * q;
        int row = c >> 3, kc = c & 7;
        cp16(baseA + (uint32_t)(row * 8 + (kc ^ (row & 7))) * 16u, Ag + c);
    }
    #pragma unroll
    for (int t0 = 0; t0 < 2; t0++) {
        int j = j0 + t0;
        if (!(sym && j < 2 * bi)) {
            #pragma unroll
            for (int q = 0; q < 8; q++) {
                int c = lane + 32 * q;
                int row = c >> 3, kc = c & 7;
                cp16(baseB[t0] + (uint32_t)(row * 8 + (kc ^ (row & 7))) * 16u,
                     Bbase + (size_t)j * 256 + c);
            }
        }
        CP_COMMIT();
    }

    // Per-thread A-row exponent terms, broadcast-packed f16x2 once.
    const int g = lane >> 2;
    const float* rlA = g_rl + ia * NROWS + bi * 64;
    uint32_t rah[8];
    #pragma unroll
    for (int mf = 0; mf < 4; mf++) {
        float r0 = rlA[mf * 16 + g];
        float r1 = rlA[mf * 16 + g + 8];
        rah[2 * mf]     = pack_h2(r0, r0);
        rah[2 * mf + 1] = pack_h2(r1, r1);
    }

    float s = 0.0f;

    // --- Mainloop: warp-private, no block sync ----------------------------
    #pragma unroll
    for (int t = 0; t < 4; t++) {
        const int j = j0 + t;
        CP_WAIT(1);                     // group t complete (t+1 may be pending)
        if (t == 0) __syncthreads();    // A visible CTA-wide (once)
        else        __syncwarp();
        if (!(sym && j < 2 * bi)) {
            const float lw = (sym && j > 2 * bi + 1) ? 1.0f : 0.0f;
            s += tile_compute(baseA, baseB[t & 1], rah,
                              g_rl + ib * NROWS + j * 32, lw, lane);
        }
        if (t < 2) {                    // prefetch slice t+2 into buf[t&1]
            int jn = j0 + t + 2;
            if (!(sym && jn < 2 * bi)) {
                #pragma unroll
                for (int q = 0; q < 8; q++) {
                    int c = lane + 32 * q;
                    int row = c >> 3, kc = c & 7;
                    cp16(baseB[t & 1] + (uint32_t)(row * 8 + (kc ^ (row & 7))) * 16u,
                         Bbase + (size_t)jn * 256 + c);
                }
            }
        }
        CP_COMMIT();                    // uniform group count (may be empty)
    }

    // Warp reduce -> one double atomic per warp
    #pragma unroll
    for (int off = 16; off > 0; off >>= 1)
        s += __shfl_down_sync(0xffffffffu, s, off);
    if (lane == 0)
        atomicAdd(&g_sums[pz], (double)s);
}

// ---------------------------------------------------------------------------
// Epilogue: 3 log-ratio terms in double
// ---------------------------------------------------------------------------
__global__ void finish_kernel(float* __restrict__ out) {
    const double norm = sqrt(2.0 * M_PI * KSIZE);
    const double inv  = 1.0 / ((double)NROWS * (double)NROWS * norm);
    double m[6];
    #pragma unroll
    for (int q = 0; q < 6; q++) m[q] = g_sums[q] * inv;
    double loss = 0.0;
    loss += log(SIGMA * sqrt(m[0] * m[1] + EPSV) / (m[3] + EPSV));
    loss += log(SIGMA * sqrt(m[0] * m[2] + EPSV) / (m[4] + EPSV));
    loss += log(SIGMA * sqrt(m[1] * m[2] + EPSV) / (m[5] + EPSV));
    out[0] = (float)loss;
}

// ---------------------------------------------------------------------------
extern "C" void kernel_launch(void* const* d_in, const int* in_sizes, int n_in,
                              void* d_out, int out_size) {
    const float* m0 = (const float*)d_in[0];
    const float* m1 = (const float*)d_in[1];
    const float* m2 = (const float*)d_in[2];
    float* out = (float*)d_out;

    fused_prep<<<(3 * NROWS) / 8, 256>>>(m0, m1, m2);
    gram_mma<<<dim3(16, 128, 6), 128>>>();
    finish_kernel<<<1, 1>>>(out);
}

// round 9
// speedup vs baseline: 1.1693x; 1.0983x over previous
#include <cuda_runtime.h>
#include <cuda_fp16.h>
#include <math.h>
#include <stdint.h>

#define NROWS 8192
#define DDIM  64
#define KSIZE 128.0
#define SIGMA 3.0
#define EPSV  1e-5

// ---------------------------------------------------------------------------
// Device-global scratch (no allocation allowed in kernel_launch)
// ---------------------------------------------------------------------------
__device__ double g_sums[6];
__device__ float  g_rl[3 * NROWS];                        // -|x|^2/(128 ln2)
__device__ __align__(16) __half g_hf[3 * NROWS * DDIM];   // f16 copies

// ---------------------------------------------------------------------------
static __device__ __forceinline__ uint32_t smem_u32(const void* p) {
    uint32_t a;
    asm("{ .reg .u64 t; cvta.to.shared.u64 t, %1; cvt.u32.u64 %0, t; }"
        : "=r"(a) : "l"(p));
    return a;
}
static __device__ __forceinline__ uint32_t pack_h2(float lo, float hi) {
    uint32_t r; asm("cvt.rn.f16x2.f32 %0, %1, %2;" : "=r"(r) : "f"(hi), "f"(lo));
    return r;
}
static __device__ __forceinline__ uint32_t ex2_h2(uint32_t x) {
    uint32_t r; asm("ex2.approx.f16x2 %0, %1;" : "=r"(r) : "r"(x));
    return r;
}
static __device__ __forceinline__ uint32_t hfma2(uint32_t a, uint32_t b, uint32_t c) {
    uint32_t r; asm("fma.rn.f16x2 %0, %1, %2, %3;" : "=r"(r) : "r"(a), "r"(b), "r"(c));
    return r;
}
static __device__ __forceinline__ float unpack_sum_h2(uint32_t p) {
    float lo, hi;
    asm("{ .reg .f16 l, u; mov.b32 {l, u}, %2;\n\t"
        "cvt.f32.f16 %0, l; cvt.f32.f16 %1, u; }"
        : "=f"(lo), "=f"(hi) : "r"(p));
    return lo + hi;
}
static __device__ __forceinline__ void ldsm_x4(uint32_t* r, uint32_t addr) {
    asm volatile("ldmatrix.sync.aligned.m8n8.x4.shared.b16 {%0,%1,%2,%3}, [%4];"
                 : "=r"(r[0]), "=r"(r[1]), "=r"(r[2]), "=r"(r[3]) : "r"(addr));
}
// f16 in, f16 accumulate: d/c are 2 packed f16x2 regs.
static __device__ __forceinline__ void mma16816_h(uint32_t* d, const uint32_t* a,
                                                  uint32_t b0, uint32_t b1) {
    asm volatile(
        "mma.sync.aligned.m16n8k16.row.col.f16.f16.f16.f16 "
        "{%0,%1}, {%2,%3,%4,%5}, {%6,%7}, {%0,%1};"
        : "+r"(d[0]), "+r"(d[1])
        : "r"(a[0]), "r"(a[1]), "r"(a[2]), "r"(a[3]), "r"(b0), "r"(b1));
}
static __device__ __forceinline__ void cp16(uint32_t dst, const void* src) {
    asm volatile("cp.async.cg.shared.global [%0], [%1], 16;" :: "r"(dst), "l"(src));
}
#define CP_COMMIT() asm volatile("cp.async.commit_group;" ::: "memory")
#define CP_WAIT(n)  asm volatile("cp.async.wait_group %0;" :: "n"(n) : "memory")

// ---------------------------------------------------------------------------
// Fused prep: f16 convert + row norms (+ zero the 6 accumulators).
// ---------------------------------------------------------------------------
__global__ void fused_prep(const float* __restrict__ m0,
                           const float* __restrict__ m1,
                           const float* __restrict__ m2) {
    const int tid = threadIdx.x;
    if (blockIdx.x == 0 && tid < 6) g_sums[tid] = 0.0;

    const int gw   = blockIdx.x * 8 + (tid >> 5);   // global warp = row id
    const int lane = tid & 31;
    if (gw >= 3 * NROWS) return;
    const int mod = gw / NROWS;
    const int row = gw - mod * NROWS;
    const float* src = (mod == 0) ? m0 : (mod == 1) ? m1 : m2;

    float2 v = ((const float2*)(src + (size_t)row * DDIM))[lane];
    __half2* dst = (__half2*)(g_hf + (size_t)gw * DDIM);
    dst[lane] = __float22half2_rn(v);

    float s = v.x * v.x + v.y * v.y;
    #pragma unroll
    for (int off = 16; off > 0; off >>= 1)
        s += __shfl_down_sync(0xffffffffu, s, off);
    if (lane == 0) g_rl[gw] = s * (float)(-1.0 / (128.0 * M_LN2));
}

// ---------------------------------------------------------------------------
// One 64x32 warp tile vs K=64, f16 accumulators (already packed f16x2).
// Epilogue per 4 elems: 2 hfma2 + 2 ex2.f16x2 + 2 hfma2.
// ---------------------------------------------------------------------------
static __device__ __forceinline__ float tile_compute(
    uint32_t baseA, uint32_t baseB, const uint32_t* rah,
    const float* __restrict__ rlB, float lw, int lane)
{
    const int tig  = lane & 3;
    const int a_r  = lane & 15;
    const int a_kh = lane >> 4;
    const int b_r  = (lane & 7) + ((lane & 16) >> 1);
    const int b_kh = (lane >> 3) & 1;

    uint32_t d[4][4][2];
    #pragma unroll
    for (int mf = 0; mf < 4; mf++)
        #pragma unroll
        for (int nf = 0; nf < 4; nf++) { d[mf][nf][0] = 0u; d[mf][nf][1] = 0u; }

    #pragma unroll
    for (int ks = 0; ks < 4; ks++) {
        uint32_t a[4][4];
        #pragma unroll
        for (int mf = 0; mf < 4; mf++) {
            int row = mf * 16 + a_r;
            int kc = ks * 2 + a_kh;
            ldsm_x4(a[mf], baseA + row * 128 + ((kc ^ (row & 7)) << 4));
        }
        uint32_t b[2][4];
        #pragma unroll
        for (int bf = 0; bf < 2; bf++) {
            int row = bf * 16 + b_r;
            int kc = ks * 2 + b_kh;
            ldsm_x4(b[bf], baseB + row * 128 + ((kc ^ (row & 7)) << 4));
        }
        #pragma unroll
        for (int mf = 0; mf < 4; mf++)
            #pragma unroll
            for (int nf = 0; nf < 4; nf++)
                mma16816_h(d[mf][nf], a[mf],
                           b[nf >> 1][(nf & 1) * 2], b[nf >> 1][(nf & 1) * 2 + 1]);
    }

    // Per-column factor pb = 2^(rb + lw), packed f16x2 per nf.
    const float C2 = (float)(1.0 / (64.0 * M_LN2));
    const uint32_t C2h = pack_h2(C2, C2);
    uint32_t pbh[4];
    #pragma unroll
    for (int nf = 0; nf < 4; nf++)
        pbh[nf] = ex2_h2(pack_h2(rlB[nf * 8 + tig * 2] + lw,
                                 rlB[nf * 8 + tig * 2 + 1] + lw));

    uint32_t acc[4] = {0u, 0u, 0u, 0u};
    #pragma unroll
    for (int mf = 0; mf < 4; mf++)
        #pragma unroll
        for (int nf = 0; nf < 4; nf++) {
            uint32_t e01 = ex2_h2(hfma2(d[mf][nf][0], C2h, rah[2 * mf]));
            uint32_t e23 = ex2_h2(hfma2(d[mf][nf][1], C2h, rah[2 * mf + 1]));
            acc[(mf & 1) * 2]     = hfma2(e01, pbh[nf], acc[(mf & 1) * 2]);
            acc[(mf & 1) * 2 + 1] = hfma2(e23, pbh[nf], acc[(mf & 1) * 2 + 1]);
        }

    return (unpack_sum_h2(acc[0]) + unpack_sum_h2(acc[1])) +
           (unpack_sum_h2(acc[2]) + unpack_sum_h2(acc[3]));
}

// ---------------------------------------------------------------------------
// Main Gram kernel: per-warp independent pipelines, 5 CTAs/SM.
// grid = (16, 128, 6): bjs (16 x 32-col slices), bi (64 rows), pair.
// CTA = 4 warps; A (64 rows, 8 KB) shared; each warp owns 4 consecutive
// 32-col B slices, double-buffered in private smem via its own cp.async
// groups. Symmetric pairs at 32-col granularity: j < 2bi skip, j in
// {2bi, 2bi+1} weight 1, j > 2bi+1 weight 2 (folded as +1 in exponent).
// ---------------------------------------------------------------------------
__global__ __launch_bounds__(128, 5) void gram_mma() {
    const int pz = blockIdx.z;
    const int pa_[6] = {0, 1, 2, 0, 0, 1};
    const int pb_[6] = {0, 1, 2, 1, 2, 2};
    const int ia = pa_[pz], ib = pb_[pz];
    const int bi = blockIdx.y, bjs = blockIdx.x;
    const bool sym = (pz < 3);
    if (sym && bjs * 16 + 15 < 2 * bi) return;       // whole CTA below diagonal

    __shared__ __align__(128) uint4 smA[512];        // 64 rows x 8 chunks, 8 KB
    __shared__ __align__(128) uint4 smB[4][2][256];  // per-warp double buffer

    const int tid = threadIdx.x;
    const int wid = tid >> 5, lane = tid & 31;
    const int j0 = bjs * 16 + wid * 4;               // this warp's first slice

    const uint4* Ag = (const uint4*)(g_hf + (size_t)ia * NROWS * DDIM) + (size_t)bi * 512;
    const uint4* Bbase = (const uint4*)(g_hf + (size_t)ib * NROWS * DDIM);

    const uint32_t baseA = smem_u32(smA);
    const uint32_t baseB[2] = { smem_u32(smB[wid][0]), smem_u32(smB[wid][1]) };

    // --- Prologue ---------------------------------------------------------
    #pragma unroll
    for (int q = 0; q < 4; q++) {
        int c = tid + 128 * q;
        int row = c >> 3, kc = c & 7;
        cp16(baseA + (uint32_t)(row * 8 + (kc ^ (row & 7))) * 16u, Ag + c);
    }
    #pragma unroll
    for (int t0 = 0; t0 < 2; t0++) {
        int j = j0 + t0;
        if (!(sym && j < 2 * bi)) {
            #pragma unroll
            for (int q = 0; q < 8; q++) {
                int c = lane + 32 * q;
                int row = c >> 3, kc = c & 7;
                cp16(baseB[t0] + (uint32_t)(row * 8 + (kc ^ (row & 7))) * 16u,
                     Bbase + (size_t)j * 256 + c);
            }
        }
        CP_COMMIT();
    }

    // Per-thread A-row exponent terms, broadcast-packed f16x2 once.
    const int g = lane >> 2;
    const float* rlA = g_rl + ia * NROWS + bi * 64;
    uint32_t rah[8];
    #pragma unroll
    for (int mf = 0; mf < 4; mf++) {
        float r0 = rlA[mf * 16 + g];
        float r1 = rlA[mf * 16 + g + 8];
        rah[2 * mf]     = pack_h2(r0, r0);
        rah[2 * mf + 1] = pack_h2(r1, r1);
    }

    float s = 0.0f;

    // --- Mainloop: warp-private, no block sync ----------------------------
    #pragma unroll
    for (int t = 0; t < 4; t++) {
        const int j = j0 + t;
        CP_WAIT(1);                     // group t complete (t+1 may be pending)
        if (t == 0) __syncthreads();    // A visible CTA-wide (once)
        else        __syncwarp();
        if (!(sym && j < 2 * bi)) {
            const float lw = (sym && j > 2 * bi + 1) ? 1.0f : 0.0f;
            s += tile_compute(baseA, baseB[t & 1], rah,
                              g_rl + ib * NROWS + j * 32, lw, lane);
        }
        if (t < 2) {                    // prefetch slice t+2 into buf[t&1]
            int jn = j0 + t + 2;
            if (!(sym && jn < 2 * bi)) {
                #pragma unroll
                for (int q = 0; q < 8; q++) {
                    int c = lane + 32 * q;
                    int row = c >> 3, kc = c & 7;
                    cp16(baseB[t & 1] + (uint32_t)(row * 8 + (kc ^ (row & 7))) * 16u,
                         Bbase + (size_t)jn * 256 + c);
                }
            }
        }
        CP_COMMIT();                    // uniform group count (may be empty)
    }

    // Warp reduce -> one double atomic per warp
    #pragma unroll
    for (int off = 16; off > 0; off >>= 1)
        s += __shfl_down_sync(0xffffffffu, s, off);
    if (lane == 0)
        atomicAdd(&g_sums[pz], (double)s);
}

// ---------------------------------------------------------------------------
// Epilogue: 3 log-ratio terms in double
// ---------------------------------------------------------------------------
__global__ void finish_kernel(float* __restrict__ out) {
    const double norm = sqrt(2.0 * M_PI * KSIZE);
    const double inv  = 1.0 / ((double)NROWS * (double)NROWS * norm);
    double m[6];
    #pragma unroll
    for (int q = 0; q < 6; q++) m[q] = g_sums[q] * inv;
    double loss = 0.0;
    loss += log(SIGMA * sqrt(m[0] * m[1] + EPSV) / (m[3] + EPSV));
    loss += log(SIGMA * sqrt(m[0] * m[2] + EPSV) / (m[4] + EPSV));
    loss += log(SIGMA * sqrt(m[1] * m[2] + EPSV) / (m[5] + EPSV));
    out[0] = (float)loss;
}

// ---------------------------------------------------------------------------
extern "C" void kernel_launch(void* const* d_in, const int* in_sizes, int n_in,
                              void* d_out, int out_size) {
    const float* m0 = (const float*)d_in[0];
    const float* m1 = (const float*)d_in[1];
    const float* m2 = (const float*)d_in[2];
    float* out = (float*)d_out;

    fused_prep<<<(3 * NROWS) / 8, 256>>>(m0, m1, m2);
    gram_mma<<<dim3(16, 128, 6), 128>>>();
    finish_kernel<<<1, 1>>>(out);
}